// round 1
// baseline (speedup 1.0000x reference)
#include <cuda_runtime.h>
#include <cuda_bf16.h>

// Problem constants (fixed by dataset)
#define BB 2
#define CC 256
#define HH 56
#define WW 56
#define NN 64
#define MM 8
#define PP 7
#define R_PER_IMG (NN + NN*MM)        // 576
#define R_TOTAL   (BB * R_PER_IMG)    // 1152
#define MAXK 12

// Per-roi axis tables: index t = r*2 + a  (a=0: y, a=1: x), then *7 + p
__device__ int   g_off[R_TOTAL * 2 * 7];
__device__ int   g_cnt[R_TOTAL * 2 * 7];
__device__ float g_wgt[R_TOTAL * 2 * 7 * MAXK];

// ---------------------------------------------------------------------------
// Kernel A: build sparse interpolation tables for every roi & axis.
// One thread per (roi, axis). Replicates reference math (floor/clamp/valid).
// ---------------------------------------------------------------------------
__global__ void prep_kernel(const float* __restrict__ boxes,
                            const float* __restrict__ gts) {
    int t = blockIdx.x * blockDim.x + threadIdx.x;
    if (t >= R_TOTAL * 2) return;
    int r = t >> 1, a = t & 1;
    int b = r / R_PER_IMG, idx = r % R_PER_IMG;

    float x1, y1, x2, y2;
    if (idx < NN) {
        const float* bx = boxes + (b * NN + idx) * 4;
        x1 = bx[0]; y1 = bx[1]; x2 = bx[2]; y2 = bx[3];
    } else {
        int n = (idx - NN) >> 3, m = (idx - NN) & 7;
        const float* bx = boxes + (b * NN + n) * 4;
        const float* gx = gts   + (b * MM + m) * 4;
        x1 = fminf(bx[0], gx[0]); y1 = fminf(bx[1], gx[1]);
        x2 = fmaxf(bx[2], gx[2]); y2 = fmaxf(bx[3], gx[3]);
    }

    float start = a ? x1 : y1;
    float len   = fmaxf(a ? (x2 - x1) : (y2 - y1), 1.0f);
    const float dimf = 56.0f;
    const int   dim  = 56;

    float bin = len / 7.0f;
    int   g   = (int)ceilf(bin);           // grid = ceil(length/P)
    float gf  = (float)g;
    float inv = 1.0f / gf;

    int base_out = t * 7;
    for (int p = 0; p < 7; p++) {
        float acc[MAXK];
        #pragma unroll
        for (int k = 0; k < MAXK; k++) acc[k] = 0.0f;
        int base = -1, hi = -1;
        float c0 = start + (float)p * bin;
        for (int s = 0; s < 8; s++) {
            if (s >= g) break;
            float coord = c0 + ((float)s + 0.5f) * bin / gf;
            if (!(coord >= -1.0f && coord <= dimf)) continue;
            float c = fmaxf(coord, 0.0f);
            int low = (int)floorf(c);
            int high; float cv;
            if (low >= dim - 1) { low = dim - 1; high = dim - 1; cv = (float)low; }
            else                { high = low + 1; cv = c; }
            float l  = cv - (float)low;
            float wl = (1.0f - l) * inv;
            float wh = l * inv;
            if (base < 0) base = low;
            int d  = low  - base;
            int d2 = high - base;
            if (d  >= 0 && d  < MAXK) acc[d]  += wl;
            if (d2 >= 0 && d2 < MAXK) acc[d2] += wh;
            if (high > hi) hi = high;
        }
        int cnt = (base < 0) ? 0 : (hi - base + 1);
        if (base < 0) base = 0;
        if (cnt > MAXK) cnt = MAXK;   // safety (bound is 10)
        g_off[base_out + p] = base;
        g_cnt[base_out + p] = cnt;
        float* wp = g_wgt + (base_out + p) * MAXK;
        #pragma unroll
        for (int k = 0; k < MAXK; k++) wp[k] = acc[k];
    }
}

// ---------------------------------------------------------------------------
// Kernel B: main compute. One CTA per (channel, image). fm slice in smem.
// Each warp owns a set of n's; per n it processes box roi (w=1) + 8 ctx rois
// (w=1/8) and accumulates the 7x7 output in registers.
// Lane -> output-cell mapping: cell0 = lane (0..31), cell1 = lane+32 (<49).
// Stage 1: lane -> column w, w0 = lane, w1 = lane+32 (valid if lane<24).
// ---------------------------------------------------------------------------
__global__ void __launch_bounds__(256, 6)
roi_main_kernel(const float* __restrict__ fm, float* __restrict__ out) {
    const int c = blockIdx.x;
    const int b = blockIdx.y;

    __shared__ float fm_s[3200];           // 56x56 + pad for lane+32 over-read
    __shared__ float tmp_s[8][7 * 56];     // per-warp stage-1 buffer

    // stage fm[b][c] into smem (3136 floats = 784 float4)
    {
        const float4* src = (const float4*)(fm + (size_t)(b * CC + c) * (HH * WW));
        float4* dst = (float4*)fm_s;
        for (int i = threadIdx.x; i < 784; i += 256) dst[i] = src[i];
        // zero the pad
        if (threadIdx.x < 64) fm_s[3136 + threadIdx.x] = 0.0f;
    }
    __syncthreads();

    const int wid  = threadIdx.x >> 5;
    const int lane = threadIdx.x & 31;
    float* tmp = tmp_s[wid];

    // per-thread stage-2 cell mapping (constant across rois)
    const int cell1 = lane + 32;
    const int p0 = lane / 7,  q0 = lane % 7;        // always valid
    const int p1 = cell1 / 7, q1 = cell1 % 7;       // valid iff cell1 < 49
    const bool has1 = (cell1 < 49);

    for (int n = wid; n < NN; n += 8) {
        float acc0 = 0.0f, acc1 = 0.0f;
        #pragma unroll 1
        for (int j = 0; j < 9; j++) {
            const int r = b * R_PER_IMG + ((j == 0) ? n : (NN + n * 8 + (j - 1)));
            const float wroi = (j == 0) ? 1.0f : 0.125f;
            const int ybase = (r * 2) * 7;
            const int xbase = ybase + 7;

            // ---- stage 1: tmp[p][w] = sum_k wY[p][k] * fm[offY+k][w] ----
            #pragma unroll 1
            for (int p = 0; p < 7; p++) {
                int off = __ldg(&g_off[ybase + p]);
                int cnt = __ldg(&g_cnt[ybase + p]);
                const float* wp = g_wgt + (size_t)(ybase + p) * MAXK;
                float a0 = 0.0f, a1 = 0.0f;
                const float* row = fm_s + off * 56 + lane;
                #pragma unroll 1
                for (int k = 0; k < cnt; k++) {
                    float wv = __ldg(wp + k);
                    a0 += wv * row[0];
                    a1 += wv * row[32];
                    row += 56;
                }
                tmp[p * 56 + lane] = a0;
                if (lane < 24) tmp[p * 56 + 32 + lane] = a1;
            }
            __syncwarp();

            // ---- stage 2: out[p][q] = sum_k wX[q][k] * tmp[p][offX+k] ----
            {
                int offx = __ldg(&g_off[xbase + q0]);
                int cntx = __ldg(&g_cnt[xbase + q0]);
                const float* wq = g_wgt + (size_t)(xbase + q0) * MAXK;
                const float* tp = tmp + p0 * 56 + offx;
                float s0 = 0.0f;
                #pragma unroll 1
                for (int k = 0; k < cntx; k++) s0 += __ldg(wq + k) * tp[k];
                acc0 += wroi * s0;
            }
            if (has1) {
                int offx = __ldg(&g_off[xbase + q1]);
                int cntx = __ldg(&g_cnt[xbase + q1]);
                const float* wq = g_wgt + (size_t)(xbase + q1) * MAXK;
                const float* tp = tmp + p1 * 56 + offx;
                float s1 = 0.0f;
                #pragma unroll 1
                for (int k = 0; k < cntx; k++) s1 += __ldg(wq + k) * tp[k];
                acc1 += wroi * s1;
            }
            __syncwarp();   // protect tmp before next roi overwrites it
        }

        // ---- store out[b][n][c][p][q] ----
        float* o = out + ((size_t)(b * NN + n) * CC + c) * (PP * PP);
        o[lane] = acc0;
        if (has1) o[cell1] = acc1;
    }
}

// ---------------------------------------------------------------------------
extern "C" void kernel_launch(void* const* d_in, const int* in_sizes, int n_in,
                              void* d_out, int out_size) {
    const float* fm    = (const float*)d_in[0];
    const float* boxes = (const float*)d_in[1];
    const float* gts   = (const float*)d_in[2];
    float* out = (float*)d_out;

    prep_kernel<<<(R_TOTAL * 2 + 127) / 128, 128>>>(boxes, gts);

    dim3 grid(CC, BB);
    roi_main_kernel<<<grid, 256>>>(fm, out);
}

// round 2
// speedup vs baseline: 2.1281x; 2.1281x over previous
#include <cuda_runtime.h>
#include <cuda_bf16.h>

// Problem constants (fixed by dataset)
#define BB 2
#define CC 256
#define HH 56
#define WW 56
#define NN 64
#define MM 8
#define PP 7
#define R_PER_IMG (NN + NN*MM)        // 576
#define R_TOTAL   (BB * R_PER_IMG)    // 1152
#define MAXK 12

// Per-roi tables. For roi r: 14 rows (7 y then 7 x), each 12 weights.
// meta = off | (cnt<<16)
__device__ int g_meta[R_TOTAL * 14];
__device__ __align__(16) float g_wgt[R_TOTAL * 14 * MAXK];

// ---------------------------------------------------------------------------
// Kernel A: build sparse interpolation tables for every roi & axis.
// One thread per (roi, axis). Replicates reference math exactly.
// ---------------------------------------------------------------------------
__global__ void prep_kernel(const float* __restrict__ boxes,
                            const float* __restrict__ gts) {
    int t = blockIdx.x * blockDim.x + threadIdx.x;
    if (t >= R_TOTAL * 2) return;
    int r = t >> 1, a = t & 1;
    int b = r / R_PER_IMG, idx = r % R_PER_IMG;

    float x1, y1, x2, y2;
    if (idx < NN) {
        const float* bx = boxes + (b * NN + idx) * 4;
        x1 = bx[0]; y1 = bx[1]; x2 = bx[2]; y2 = bx[3];
    } else {
        int n = (idx - NN) >> 3, m = (idx - NN) & 7;
        const float* bx = boxes + (b * NN + n) * 4;
        const float* gx = gts   + (b * MM + m) * 4;
        x1 = fminf(bx[0], gx[0]); y1 = fminf(bx[1], gx[1]);
        x2 = fmaxf(bx[2], gx[2]); y2 = fmaxf(bx[3], gx[3]);
    }

    float start = a ? x1 : y1;
    float len   = fmaxf(a ? (x2 - x1) : (y2 - y1), 1.0f);
    const float dimf = 56.0f;
    const int   dim  = 56;

    float bin = len / 7.0f;
    int   g   = (int)ceilf(bin);           // grid = ceil(length/P)
    float gf  = (float)g;
    float inv = 1.0f / gf;

    int base_out = t * 7;                  // == r*14 + a*7
    for (int p = 0; p < 7; p++) {
        float acc[MAXK];
        #pragma unroll
        for (int k = 0; k < MAXK; k++) acc[k] = 0.0f;
        int base = -1, hi = -1;
        float c0 = start + (float)p * bin;
        for (int s = 0; s < 8; s++) {
            if (s >= g) break;
            float coord = c0 + ((float)s + 0.5f) * bin / gf;
            if (!(coord >= -1.0f && coord <= dimf)) continue;
            float c = fmaxf(coord, 0.0f);
            int low = (int)floorf(c);
            int high; float cv;
            if (low >= dim - 1) { low = dim - 1; high = dim - 1; cv = (float)low; }
            else                { high = low + 1; cv = c; }
            float l  = cv - (float)low;
            float wl = (1.0f - l) * inv;
            float wh = l * inv;
            if (base < 0) base = low;
            int d  = low  - base;
            int d2 = high - base;
            if (d  >= 0 && d  < MAXK) acc[d]  += wl;
            if (d2 >= 0 && d2 < MAXK) acc[d2] += wh;
            if (high > hi) hi = high;
        }
        int cnt = (base < 0) ? 0 : (hi - base + 1);
        if (base < 0) base = 0;
        if (cnt > MAXK) cnt = MAXK;   // safety (true bound is 10)
        g_meta[base_out + p] = base | (cnt << 16);
        float* wp = g_wgt + (size_t)(base_out + p) * MAXK;
        #pragma unroll
        for (int k = 0; k < MAXK; k++) wp[k] = acc[k];
    }
}

// ---------------------------------------------------------------------------
// Kernel B: main compute. One CTA per (channel-pair, image, n-quarter).
// fm for 2 channels interleaved in smem: fm_s[h][w(64)][2ch] -> LDS.64 serves
// both channels. Per-roi weights staged into warp smem (broadcast LDS).
// Each warp: 2 n's; per n: box roi (w=1) + 8 ctx rois (w=1/8), 7x7 out
// accumulated in registers for both channels.
// ---------------------------------------------------------------------------
__global__ void __launch_bounds__(256)
roi_main_kernel(const float* __restrict__ fm, float* __restrict__ out) {
    const int cp = blockIdx.x;          // channel pair: c0 = 2*cp
    const int b  = blockIdx.y;
    const int nbase = blockIdx.z * 16;  // 16 n per CTA

    __shared__ float2 fm_s[HH * 64];        // [h][w], .x=ch0 .y=ch1  (28672 B)
    __shared__ float2 tmp_s[8][7 * 65];     // per-warp, padded rows  (29120 B)
    __shared__ float4 wtab4[8][42];         // per-warp roi weights   (5376 B)
    __shared__ int    meta_s[8][14];        //                        (448 B)

    const int tid = threadIdx.x;
    const int c0 = cp * 2;

    // ---- stage fm[b][c0] and fm[b][c0+1] interleaved ----
    {
        const float4* s0 = (const float4*)(fm + ((size_t)(b * CC + c0)     ) * (HH * WW));
        const float4* s1 = (const float4*)(fm + ((size_t)(b * CC + c0 + 1)) * (HH * WW));
        for (int i = tid; i < 784; i += 256) {       // 784 float4 per channel
            float4 v0 = s0[i];
            float4 v1 = s1[i];
            int h = i / 14, w = (i % 14) * 4;
            float2* d = &fm_s[h * 64 + w];
            d[0] = make_float2(v0.x, v1.x);
            d[1] = make_float2(v0.y, v1.y);
            d[2] = make_float2(v0.z, v1.z);
            d[3] = make_float2(v0.w, v1.w);
        }
        for (int i = tid; i < HH * 8; i += 256) {    // zero pad cols 56..63
            int h = i / 8, w = 56 + (i % 8);
            fm_s[h * 64 + w] = make_float2(0.f, 0.f);
        }
    }
    __syncthreads();

    const int wid  = tid >> 5;
    const int lane = tid & 31;
    float2* tmpw = tmp_s[wid];
    const float* wt = (const float*)wtab4[wid];
    const int* mt = meta_s[wid];

    // stage-2 cell mapping (constant): cell0 = lane, cell1 = lane+32
    const int p0 = lane / 7,        q0 = lane % 7;
    const int p1 = (lane + 32) / 7, q1 = (lane + 32) % 7;
    const bool has1 = (lane + 32 < 49);

    #pragma unroll 1
    for (int nn = 0; nn < 2; nn++) {
        const int n = nbase + wid + nn * 8;
        float2 acc0 = make_float2(0.f, 0.f);
        float2 acc1 = make_float2(0.f, 0.f);

        #pragma unroll 1
        for (int j = 0; j < 9; j++) {
            const int r = b * R_PER_IMG + ((j == 0) ? n : (NN + n * 8 + (j - 1)));
            const float wroi = (j == 0) ? 1.0f : 0.125f;

            // ---- stage per-roi weights + meta into warp smem ----
            {
                const float4* gw = (const float4*)(g_wgt + (size_t)r * 168);
                wtab4[wid][lane] = __ldg(gw + lane);
                if (lane < 10) wtab4[wid][lane + 32] = __ldg(gw + lane + 32);
                if (lane < 14) meta_s[wid][lane] = __ldg(&g_meta[r * 14 + lane]);
            }
            __syncwarp();

            // ---- stage 1: tmp[p][w] = sum_k wY[p][k] * fm[offY+k][w] ----
            #pragma unroll 1
            for (int p = 0; p < 7; p++) {
                int meta = mt[p];
                int off = meta & 0xFFFF, cnt = meta >> 16;
                const float* wp = wt + p * 12;
                const float2* row = fm_s + off * 64 + lane;
                float2 a0 = make_float2(0.f, 0.f);
                float2 a1 = make_float2(0.f, 0.f);
                #pragma unroll 2
                for (int k = 0; k < cnt; k++) {
                    float wv = wp[k];
                    float2 f0 = row[0];
                    float2 f1 = row[32];
                    a0.x += wv * f0.x; a0.y += wv * f0.y;
                    a1.x += wv * f1.x; a1.y += wv * f1.y;
                    row += 64;
                }
                tmpw[p * 65 + lane] = a0;
                if (lane < 24) tmpw[p * 65 + 32 + lane] = a1;
            }
            __syncwarp();

            // ---- stage 2: out[p][q] = sum_k wX[q][k] * tmp[p][offX+k] ----
            {
                int meta = mt[7 + q0];
                int off = meta & 0xFFFF, cnt = meta >> 16;
                const float* wq = wt + (7 + q0) * 12;
                const float2* tp = tmpw + p0 * 65 + off;
                float2 s = make_float2(0.f, 0.f);
                #pragma unroll 2
                for (int k = 0; k < cnt; k++) {
                    float wv = wq[k];
                    float2 v = tp[k];
                    s.x += wv * v.x; s.y += wv * v.y;
                }
                acc0.x += wroi * s.x; acc0.y += wroi * s.y;
            }
            if (has1) {
                int meta = mt[7 + q1];
                int off = meta & 0xFFFF, cnt = meta >> 16;
                const float* wq = wt + (7 + q1) * 12;
                const float2* tp = tmpw + p1 * 65 + off;
                float2 s = make_float2(0.f, 0.f);
                #pragma unroll 2
                for (int k = 0; k < cnt; k++) {
                    float wv = wq[k];
                    float2 v = tp[k];
                    s.x += wv * v.x; s.y += wv * v.y;
                }
                acc1.x += wroi * s.x; acc1.y += wroi * s.y;
            }
            __syncwarp();   // tmp + wtab reuse safety before next roi
        }

        // ---- store out[b][n][c][p][q], channels c0 and c0+1 ----
        float* o = out + ((size_t)(b * NN + n) * CC + c0) * (PP * PP);
        o[lane]      = acc0.x;
        o[49 + lane] = acc0.y;
        if (has1) {
            o[lane + 32]      = acc1.x;
            o[49 + lane + 32] = acc1.y;
        }
    }
}

// ---------------------------------------------------------------------------
extern "C" void kernel_launch(void* const* d_in, const int* in_sizes, int n_in,
                              void* d_out, int out_size) {
    const float* fm    = (const float*)d_in[0];
    const float* boxes = (const float*)d_in[1];
    const float* gts   = (const float*)d_in[2];
    float* out = (float*)d_out;

    prep_kernel<<<(R_TOTAL * 2 + 127) / 128, 128>>>(boxes, gts);

    dim3 grid(CC / 2, BB, 4);
    roi_main_kernel<<<grid, 256>>>(fm, out);
}

// round 3
// speedup vs baseline: 2.1542x; 1.0123x over previous
#include <cuda_runtime.h>
#include <cuda_bf16.h>

// Problem constants (fixed by dataset)
#define BB 2
#define CC 256
#define HH 56
#define WW 56
#define NN 64
#define MM 8
#define PP 7
#define R_PER_IMG (NN + NN*MM)        // 576
#define R_TOTAL   (BB * R_PER_IMG)    // 1152
#define MAXK 12

// Per-roi tables.
// g_meta[r*16 + row], row 0..6 = y rows, 7..13 = x rows. meta = off | (cnt<<8)
// g_rinfo[r] = x_lo | (nch<<16)
// g_wgt[(r*14+row)*12 + k], zero-padded to 12, 16B aligned per row (48B rows)
__device__ int   g_meta[R_TOTAL * 16];
__device__ int   g_rinfo[R_TOTAL];
__device__ __align__(16) float g_wgt[R_TOTAL * 14 * MAXK];

// ---------------------------------------------------------------------------
// Kernel A: build sparse interpolation tables for every roi & axis.
// One thread per (roi, axis). Replicates reference math exactly.
// ---------------------------------------------------------------------------
__global__ void prep_kernel(const float* __restrict__ boxes,
                            const float* __restrict__ gts) {
    int t = blockIdx.x * blockDim.x + threadIdx.x;
    if (t >= R_TOTAL * 2) return;
    int r = t >> 1, a = t & 1;
    int b = r / R_PER_IMG, idx = r % R_PER_IMG;

    float x1, y1, x2, y2;
    if (idx < NN) {
        const float* bx = boxes + (b * NN + idx) * 4;
        x1 = bx[0]; y1 = bx[1]; x2 = bx[2]; y2 = bx[3];
    } else {
        int n = (idx - NN) >> 3, m = (idx - NN) & 7;
        const float* bx = boxes + (b * NN + n) * 4;
        const float* gx = gts   + (b * MM + m) * 4;
        x1 = fminf(bx[0], gx[0]); y1 = fminf(bx[1], gx[1]);
        x2 = fmaxf(bx[2], gx[2]); y2 = fmaxf(bx[3], gx[3]);
    }

    float start = a ? x1 : y1;
    float len   = fmaxf(a ? (x2 - x1) : (y2 - y1), 1.0f);
    const float dimf = 56.0f;
    const int   dim  = 56;

    float bin = len / 7.0f;
    int   g   = (int)ceilf(bin);           // grid = ceil(length/P)
    float gf  = (float)g;
    float inv = 1.0f / gf;

    int lo_min = 1 << 20, hi_max = 0;
    for (int p = 0; p < 7; p++) {
        float acc[MAXK];
        #pragma unroll
        for (int k = 0; k < MAXK; k++) acc[k] = 0.0f;
        int base = -1, hi = -1;
        float c0 = start + (float)p * bin;
        for (int s = 0; s < 8; s++) {
            if (s >= g) break;
            float coord = c0 + ((float)s + 0.5f) * bin / gf;
            if (!(coord >= -1.0f && coord <= dimf)) continue;
            float c = fmaxf(coord, 0.0f);
            int low = (int)floorf(c);
            int high; float cv;
            if (low >= dim - 1) { low = dim - 1; high = dim - 1; cv = (float)low; }
            else                { high = low + 1; cv = c; }
            float l  = cv - (float)low;
            float wl = (1.0f - l) * inv;
            float wh = l * inv;
            if (base < 0) base = low;
            int d  = low  - base;
            int d2 = high - base;
            if (d  >= 0 && d  < MAXK) acc[d]  += wl;
            if (d2 >= 0 && d2 < MAXK) acc[d2] += wh;
            if (high > hi) hi = high;
        }
        int cnt = (base < 0) ? 0 : (hi - base + 1);
        if (base < 0) base = 0;
        if (cnt > MAXK) cnt = MAXK;   // safety (true bound is 10)
        if (base < lo_min) lo_min = base;
        if (base + cnt > hi_max) hi_max = base + cnt;
        g_meta[r * 16 + a * 7 + p] = base | (cnt << 8);
        float* wp = g_wgt + (size_t)((r * 14 + a * 7 + p)) * MAXK;
        #pragma unroll
        for (int k = 0; k < MAXK; k++) wp[k] = acc[k];
    }
    if (a == 1) {
        int span = hi_max - lo_min;
        if (span < 1) { lo_min = 0; span = 1; }
        int nch = (span > 32) ? 2 : 1;
        g_rinfo[r] = lo_min | (nch << 16);
    }
}

// ---------------------------------------------------------------------------
// Kernel B: main compute. One CTA per (channel-pair, image, n-sixteenth).
// fm for 2 channels interleaved in smem (64-col stride, fully zero-padded).
// 16 warps, one n each. Per n: box roi + 8 ctx rois. Stage-1 computes only
// the roi's x-window (1 or 2 chunks of 32 cols). Weights live in registers
// (3x LDG.128 per row, zero-padded), k-loop unrolled in groups of 4.
// ---------------------------------------------------------------------------
#define S1G(W) { \
    float2 f0 = cc[0], f1 = cc[64], f2 = cc[128], f3 = cc[192]; \
    a.x += W.x * f0.x + W.y * f1.x + W.z * f2.x + W.w * f3.x; \
    a.y += W.x * f0.y + W.y * f1.y + W.z * f2.y + W.w * f3.y; \
    cc += 256; }

#define S2G(U, base) { \
    float2 t0 = tp[(base)], t1 = tp[(base)+1], t2 = tp[(base)+2], t3 = tp[(base)+3]; \
    s.x += U.x * t0.x + U.y * t1.x + U.z * t2.x + U.w * t3.x; \
    s.y += U.x * t0.y + U.y * t1.y + U.z * t2.y + U.w * t3.y; }

#define TSTRIDE 69

__global__ void __launch_bounds__(512, 2)
roi_main_kernel(const float* __restrict__ fm, float* __restrict__ out) {
    const int cp = blockIdx.x;          // channel pair: c0 = 2*cp
    const int b  = blockIdx.y;
    const int nbase = blockIdx.z * 16;  // 16 n per CTA, one per warp

    __shared__ float2 fm_s[64 * 64];              // 32768 B, fully initialized
    __shared__ float2 tmp_s[16][7 * TSTRIDE];     // 61824 B

    const int tid = threadIdx.x;
    const int c0 = cp * 2;

    // ---- stage fm[b][c0..c0+1] interleaved; zero all padding ----
    {
        const float4* s0 = (const float4*)(fm + ((size_t)(b * CC + c0)     ) * (HH * WW));
        const float4* s1 = (const float4*)(fm + ((size_t)(b * CC + c0 + 1)) * (HH * WW));
        for (int i = tid; i < 784; i += 512) {       // 784 float4 per channel
            float4 v0 = s0[i];
            float4 v1 = s1[i];
            int h = i / 14, w = (i % 14) * 4;
            float2* d = &fm_s[h * 64 + w];
            d[0] = make_float2(v0.x, v1.x);
            d[1] = make_float2(v0.y, v1.y);
            d[2] = make_float2(v0.z, v1.z);
            d[3] = make_float2(v0.w, v1.w);
        }
        const float2 z2 = make_float2(0.f, 0.f);
        for (int i = tid; i < 512; i += 512) fm_s[56 * 64 + i] = z2;   // rows 56..63
        for (int i = tid; i < 448; i += 512) {                          // cols 56..63
            int h = i >> 3, w = 56 + (i & 7);
            fm_s[h * 64 + w] = z2;
        }
    }
    __syncthreads();

    const int wid  = tid >> 5;
    const int lane = tid & 31;
    float2* tmpw = tmp_s[wid];

    // stage-2 cell mapping (constant): cell0 = lane, cell1 = lane+32
    const int p0 = lane / 7,        q0 = lane % 7;
    const int p1 = (lane + 32) / 7, q1 = (lane + 32) % 7;
    const bool has1 = (lane + 32 < 49);

    const int n = nbase + wid;

    float2 accb0 = make_float2(0.f, 0.f), accb1 = make_float2(0.f, 0.f);
    float2 accx0 = make_float2(0.f, 0.f), accx1 = make_float2(0.f, 0.f);

    #pragma unroll 1
    for (int j = 0; j < 9; j++) {
        const int r = b * R_PER_IMG + ((j == 0) ? n : (NN + n * 8 + (j - 1)));
        const int rinfo = __ldg(&g_rinfo[r]);
        const int xlo = rinfo & 0xFFFF;
        const int nch = rinfo >> 16;
        const int mbase = r * 16;
        const float* wbase = g_wgt + (size_t)r * 168;

        // ---- stage 1: tmp[p][col] for col in x-window ----
        #pragma unroll 1
        for (int p = 0; p < 7; p++) {
            int meta = __ldg(&g_meta[mbase + p]);
            int off = meta & 0xFF, cnt = meta >> 8;
            const float4* wp4 = (const float4*)(wbase + p * 12);
            float4 w0 = __ldg(wp4);
            float4 w1 = __ldg(wp4 + 1);
            float4 w2 = __ldg(wp4 + 2);

            // chunk 0
            {
                const float2* cc = fm_s + off * 64 + xlo + lane;
                float2 a = make_float2(0.f, 0.f);
                S1G(w0);
                if (cnt > 4) { S1G(w1); if (cnt > 8) S1G(w2); }
                tmpw[p * TSTRIDE + lane] = a;
            }
            // chunk 1 (warp-uniform predicate)
            if (nch == 2) {
                const float2* cc = fm_s + off * 64 + xlo + 32 + lane;
                float2 a = make_float2(0.f, 0.f);
                S1G(w0);
                if (cnt > 4) { S1G(w1); if (cnt > 8) S1G(w2); }
                tmpw[p * TSTRIDE + 32 + lane] = a;
            }
            // zero tail so stage-2's zero-weight reads stay finite
            if (lane < 4) tmpw[p * TSTRIDE + nch * 32 + lane] = make_float2(0.f, 0.f);
        }
        __syncwarp();

        // ---- stage 2: out[p][q] = sum_k wX[q][k] * tmp[p][offX-xlo+k] ----
        float2 s0v, s1v;
        {
            int meta = __ldg(&g_meta[mbase + 7 + q0]);
            int off = meta & 0xFF, cnt = meta >> 8;
            const float4* uq4 = (const float4*)(wbase + (7 + q0) * 12);
            float4 u0 = __ldg(uq4);
            float4 u1 = __ldg(uq4 + 1);
            float4 u2 = __ldg(uq4 + 2);
            const float2* tp = tmpw + p0 * TSTRIDE + (off - xlo);
            float2 s = make_float2(0.f, 0.f);
            S2G(u0, 0);
            if (cnt > 4) { S2G(u1, 4); if (cnt > 8) S2G(u2, 8); }
            s0v = s;
        }
        if (has1) {
            int meta = __ldg(&g_meta[mbase + 7 + q1]);
            int off = meta & 0xFF, cnt = meta >> 8;
            const float4* uq4 = (const float4*)(wbase + (7 + q1) * 12);
            float4 u0 = __ldg(uq4);
            float4 u1 = __ldg(uq4 + 1);
            float4 u2 = __ldg(uq4 + 2);
            const float2* tp = tmpw + p1 * TSTRIDE + (off - xlo);
            float2 s = make_float2(0.f, 0.f);
            S2G(u0, 0);
            if (cnt > 4) { S2G(u1, 4); if (cnt > 8) S2G(u2, 8); }
            s1v = s;
        } else {
            s1v = make_float2(0.f, 0.f);
        }

        if (j == 0) {
            accb0 = s0v; accb1 = s1v;
        } else {
            accx0.x += s0v.x; accx0.y += s0v.y;
            accx1.x += s1v.x; accx1.y += s1v.y;
        }
        __syncwarp();   // tmp reuse safety before next roi
    }

    // ---- combine box + mean(ctx) and store out[b][n][c][p][q] ----
    float* o = out + ((size_t)(b * NN + n) * CC + c0) * (PP * PP);
    o[lane]      = accb0.x + 0.125f * accx0.x;
    o[49 + lane] = accb0.y + 0.125f * accx0.y;
    if (has1) {
        o[lane + 32]      = accb1.x + 0.125f * accx1.x;
        o[49 + lane + 32] = accb1.y + 0.125f * accx1.y;
    }
}

// ---------------------------------------------------------------------------
extern "C" void kernel_launch(void* const* d_in, const int* in_sizes, int n_in,
                              void* d_out, int out_size) {
    const float* fm    = (const float*)d_in[0];
    const float* boxes = (const float*)d_in[1];
    const float* gts   = (const float*)d_in[2];
    float* out = (float*)d_out;

    prep_kernel<<<(R_TOTAL * 2 + 127) / 128, 128>>>(boxes, gts);

    dim3 grid(CC / 2, BB, 4);
    roi_main_kernel<<<grid, 512>>>(fm, out);
}

// round 4
// speedup vs baseline: 2.3194x; 1.0767x over previous
#include <cuda_runtime.h>
#include <cuda_bf16.h>

// Problem constants (fixed by dataset)
#define BB 2
#define CC 256
#define HH 56
#define WW 56
#define NN 64
#define MM 8
#define PP 7
#define R_PER_IMG (NN + NN*MM)        // 576
#define R_TOTAL   (BB * R_PER_IMG)    // 1152
#define MAXK 12

// Per-roi tables.
// g_meta[r*16 + row], row 0..6 = y rows (p), 7..13 = x rows (q). meta = off | (cnt<<8)
// g_yinfo[r] = ylo | (span4<<8)   (span4 = y-support span rounded up to 4)
// g_wgt[(r*14+row)*12 + k], zero-padded to 12 floats per row, 16B aligned
__device__ int   g_meta[R_TOTAL * 16];
__device__ int   g_yinfo[R_TOTAL];
__device__ __align__(16) float g_wgt[R_TOTAL * 14 * MAXK];

// ---------------------------------------------------------------------------
// Kernel A: build sparse interpolation tables for every roi & axis.
// One thread per (roi, axis). Replicates reference math exactly.
// ---------------------------------------------------------------------------
__global__ void prep_kernel(const float* __restrict__ boxes,
                            const float* __restrict__ gts) {
    int t = blockIdx.x * blockDim.x + threadIdx.x;
    if (t >= R_TOTAL * 2) return;
    int r = t >> 1, a = t & 1;
    int b = r / R_PER_IMG, idx = r % R_PER_IMG;

    float x1, y1, x2, y2;
    if (idx < NN) {
        const float* bx = boxes + (b * NN + idx) * 4;
        x1 = bx[0]; y1 = bx[1]; x2 = bx[2]; y2 = bx[3];
    } else {
        int n = (idx - NN) >> 3, m = (idx - NN) & 7;
        const float* bx = boxes + (b * NN + n) * 4;
        const float* gx = gts   + (b * MM + m) * 4;
        x1 = fminf(bx[0], gx[0]); y1 = fminf(bx[1], gx[1]);
        x2 = fmaxf(bx[2], gx[2]); y2 = fmaxf(bx[3], gx[3]);
    }

    float start = a ? x1 : y1;
    float len   = fmaxf(a ? (x2 - x1) : (y2 - y1), 1.0f);
    const float dimf = 56.0f;
    const int   dim  = 56;

    float bin = len / 7.0f;
    int   g   = (int)ceilf(bin);           // grid = ceil(length/P)
    float gf  = (float)g;
    float inv = 1.0f / gf;

    int lo_min = 1 << 20, hi_max = -1;
    for (int p = 0; p < 7; p++) {
        float acc[MAXK];
        #pragma unroll
        for (int k = 0; k < MAXK; k++) acc[k] = 0.0f;
        int base = -1, hi = -1;
        float c0 = start + (float)p * bin;
        for (int s = 0; s < 8; s++) {
            if (s >= g) break;
            float coord = c0 + ((float)s + 0.5f) * bin / gf;
            if (!(coord >= -1.0f && coord <= dimf)) continue;
            float c = fmaxf(coord, 0.0f);
            int low = (int)floorf(c);
            int high; float cv;
            if (low >= dim - 1) { low = dim - 1; high = dim - 1; cv = (float)low; }
            else                { high = low + 1; cv = c; }
            float l  = cv - (float)low;
            float wl = (1.0f - l) * inv;
            float wh = l * inv;
            if (base < 0) base = low;
            int d  = low  - base;
            int d2 = high - base;
            if (d  >= 0 && d  < MAXK) acc[d]  += wl;
            if (d2 >= 0 && d2 < MAXK) acc[d2] += wh;
            if (high > hi) hi = high;
        }
        int cnt = (base < 0) ? 0 : (hi - base + 1);
        if (base < 0) base = 0;
        if (cnt > MAXK) cnt = MAXK;   // safety (true bound is 10)
        if (base < lo_min) lo_min = base;
        if (base + cnt > hi_max) hi_max = base + cnt;
        g_meta[r * 16 + a * 7 + p] = base | (cnt << 8);
        float* wp = g_wgt + (size_t)((r * 14 + a * 7 + p)) * MAXK;
        #pragma unroll
        for (int k = 0; k < MAXK; k++) wp[k] = acc[k];
    }
    if (a == 0) {
        int lo = lo_min, span = hi_max - lo_min;
        if (span < 1) { lo = 0; span = 1; }
        int span4 = (span + 3) & ~3;
        g_yinfo[r] = lo | (span4 << 8);
    }
}

// ---------------------------------------------------------------------------
// Kernel B: main compute. One CTA per (channel-pair, image, n-sixteenth).
// fm for 2 channels interleaved in smem (66-col row stride, zero-padded).
// 16 warps, one n each. Per n: box roi + 8 ctx rois.
// Stage 1 (x-interp first): lanes 0..27 map to (hsub = lane/7, q = lane%7);
//   iterate y-support rows in groups of 4, each lane reads its exact
//   cnt_x-contiguous float2s. x-weights in registers.
// Stage 2 (y-interp): lane -> output cell(s), reads tmp with stride 7,
//   y-weights in registers.
// ---------------------------------------------------------------------------
#define S1G(W, base) { \
    float2 f0 = cc[(base)], f1 = cc[(base)+1], f2 = cc[(base)+2], f3 = cc[(base)+3]; \
    a.x += W.x * f0.x + W.y * f1.x + W.z * f2.x + W.w * f3.x; \
    a.y += W.x * f0.y + W.y * f1.y + W.z * f2.y + W.w * f3.y; }

#define S2G(U, base) { \
    float2 t0 = tp[((base)  )*7], t1 = tp[((base)+1)*7], \
           t2 = tp[((base)+2)*7], t3 = tp[((base)+3)*7]; \
    s.x += U.x * t0.x + U.y * t1.x + U.z * t2.x + U.w * t3.x; \
    s.y += U.x * t0.y + U.y * t1.y + U.z * t2.y + U.w * t3.y; }

#define FSTRIDE 66

__global__ void __launch_bounds__(512, 2)
roi_main_kernel(const float* __restrict__ fm, float* __restrict__ out) {
    const int cp = blockIdx.x;          // channel pair: c0 = 2*cp
    const int b  = blockIdx.y;
    const int nbase = blockIdx.z * 16;  // 16 n per CTA, one per warp

    __shared__ float2 fm_s[64 * FSTRIDE];       // 33792 B, fully initialized
    __shared__ float2 tmp_s[16][64 * 7];        // 57344 B

    const int tid = threadIdx.x;
    const int c0 = cp * 2;

    // ---- stage fm[b][c0..c0+1] interleaved; zero all padding + tmp ----
    {
        const float2 z2 = make_float2(0.f, 0.f);
        // zero rows 56..63 fully, and cols 56..65 of rows 0..55
        for (int i = tid; i < 8 * FSTRIDE; i += 512) fm_s[56 * FSTRIDE + i] = z2;
        for (int i = tid; i < 56 * 10; i += 512) {
            int h = i / 10, w = 56 + (i % 10);
            fm_s[h * FSTRIDE + w] = z2;
        }
        // zero tmp (stage-2 over-reads must stay finite)
        float2* tz = &tmp_s[0][0];
        for (int i = tid; i < 16 * 64 * 7; i += 512) tz[i] = z2;

        const float4* s0 = (const float4*)(fm + ((size_t)(b * CC + c0)     ) * (HH * WW));
        const float4* s1 = (const float4*)(fm + ((size_t)(b * CC + c0 + 1)) * (HH * WW));
        for (int i = tid; i < 784; i += 512) {       // 784 float4 per channel
            float4 v0 = s0[i];
            float4 v1 = s1[i];
            int h = i / 14, w = (i % 14) * 4;
            float2* d = &fm_s[h * FSTRIDE + w];
            d[0] = make_float2(v0.x, v1.x);
            d[1] = make_float2(v0.y, v1.y);
            d[2] = make_float2(v0.z, v1.z);
            d[3] = make_float2(v0.w, v1.w);
        }
    }
    __syncthreads();

    const int wid  = tid >> 5;
    const int lane = tid & 31;
    float2* tmpw = tmp_s[wid];

    // stage-1 lane mapping: lanes 0..27 -> (hsub, qx)
    const int qx   = lane % 7;
    const int hsub = lane / 7;
    const bool act1 = (lane < 28);

    // stage-2 cell mapping: cell0 = lane, cell1 = lane+32
    const int p0 = lane / 7,        q0 = lane % 7;
    const int p1 = (lane + 32) / 7, q1 = (lane + 32) % 7;
    const bool has1 = (lane + 32 < 49);

    const int n = nbase + wid;

    float2 acc0 = make_float2(0.f, 0.f);
    float2 acc1 = make_float2(0.f, 0.f);

    #pragma unroll 1
    for (int j = 0; j < 9; j++) {
        const int r = b * R_PER_IMG + ((j == 0) ? n : (NN + n * 8 + (j - 1)));
        const float wroi = (j == 0) ? 1.0f : 0.125f;
        const int yinfo = __ldg(&g_yinfo[r]);
        const int ylo   = yinfo & 0xFF;
        const int span4 = yinfo >> 8;
        const int mbase = r * 16;
        const float* wbase = g_wgt + (size_t)r * 168;

        // ---- stage 1: x-interp. tmp[h][q] = sum_k wX[q][k]*fm[ylo+h][offx_q+k]
        {
            int metax = __ldg(&g_meta[mbase + 7 + qx]);
            int offx = metax & 0xFF, cntx = metax >> 8;
            const float4* wx4 = (const float4*)(wbase + (7 + qx) * 12);
            float4 wx0 = __ldg(wx4);
            float4 wx1 = __ldg(wx4 + 1);
            float4 wx2 = __ldg(wx4 + 2);
            #pragma unroll 1
            for (int hb = 0; hb < span4; hb += 4) {
                if (act1) {
                    int h = hb + hsub;
                    const float2* cc = fm_s + (ylo + h) * FSTRIDE + offx;
                    float2 a = make_float2(0.f, 0.f);
                    S1G(wx0, 0);
                    if (cntx > 4) { S1G(wx1, 4); if (cntx > 8) S1G(wx2, 8); }
                    tmpw[h * 7 + qx] = a;
                }
            }
        }
        __syncwarp();

        // ---- stage 2: y-interp. out[p][q] = sum_k wY[p][k]*tmp[offy_p-ylo+k][q]
        {
            int metay = __ldg(&g_meta[mbase + p0]);
            int offy = metay & 0xFF, cnty = metay >> 8;
            const float4* wy4 = (const float4*)(wbase + p0 * 12);
            float4 u0 = __ldg(wy4);
            float4 u1 = __ldg(wy4 + 1);
            float4 u2 = __ldg(wy4 + 2);
            const float2* tp = tmpw + (offy - ylo) * 7 + q0;
            float2 s = make_float2(0.f, 0.f);
            S2G(u0, 0);
            if (cnty > 4) { S2G(u1, 4); if (cnty > 8) S2G(u2, 8); }
            acc0.x += wroi * s.x; acc0.y += wroi * s.y;
        }
        if (has1) {
            int metay = __ldg(&g_meta[mbase + p1]);
            int offy = metay & 0xFF, cnty = metay >> 8;
            const float4* wy4 = (const float4*)(wbase + p1 * 12);
            float4 u0 = __ldg(wy4);
            float4 u1 = __ldg(wy4 + 1);
            float4 u2 = __ldg(wy4 + 2);
            const float2* tp = tmpw + (offy - ylo) * 7 + q1;
            float2 s = make_float2(0.f, 0.f);
            S2G(u0, 0);
            if (cnty > 4) { S2G(u1, 4); if (cnty > 8) S2G(u2, 8); }
            acc1.x += wroi * s.x; acc1.y += wroi * s.y;
        }
        __syncwarp();   // tmp reuse safety before next roi
    }

    // ---- store out[b][n][c][p][q], channels c0 and c0+1 ----
    float* o = out + ((size_t)(b * NN + n) * CC + c0) * (PP * PP);
    o[lane]      = acc0.x;
    o[49 + lane] = acc0.y;
    if (has1) {
        o[lane + 32]      = acc1.x;
        o[49 + lane + 32] = acc1.y;
    }
}

// ---------------------------------------------------------------------------
extern "C" void kernel_launch(void* const* d_in, const int* in_sizes, int n_in,
                              void* d_out, int out_size) {
    const float* fm    = (const float*)d_in[0];
    const float* boxes = (const float*)d_in[1];
    const float* gts   = (const float*)d_in[2];
    float* out = (float*)d_out;

    prep_kernel<<<(R_TOTAL * 2 + 127) / 128, 128>>>(boxes, gts);

    dim3 grid(CC / 2, BB, 4);
    roi_main_kernel<<<grid, 512>>>(fm, out);
}